// round 11
// baseline (speedup 1.0000x reference)
#include <cuda_runtime.h>
#include <cuda_bf16.h>
#include <cstdint>

// Gather: out[i, y, x, c] = logits[i * N_SP + segments[i, y, x], c]
//   logits:   [16*512, 5] fp32 (10 KB per image, TMA bulk-loaded into smem)
//   segments: [16, 512, 512] int32 (8 KB tile per block, TMA bulk-loaded)
//   out:      [16, 512, 512, 5] fp32
//
// R11: LSU-budget analysis of R10 shows STG.128 issue cost (~12cyc/warp-instr)
// is ~37% of the binding LSU/crossbar budget. Replace direct STG with
// conflict-free STS.128 into FOUR independent 10KB staging buffers (no reuse,
// so no in-loop wait_group — R5's failure mode) drained by per-iter
// cp.async.bulk S->G stores; single wait at block exit.
// 640 threads x ITERS=4 (per-iter float stride 2560 % 5 == 0 keeps the
// r-constant-lane hot loop). 59KB dynamic smem, 3 blocks/SM.

#define N_IMG 16
#define SIZE  512
#define N_SP  512
#define WAY   5
#define PIX_PER_IMG    (SIZE * SIZE)            // 262144
#define VEC_PER_IMG    (PIX_PER_IMG * WAY / 4)  // 327680 float4
#define LOGITS_PER_IMG (N_SP * WAY)             // 2560 floats = 10240 B

#define THREADS 640
#define ITERS 4
#define VEC_PER_BLOCK  (THREADS * ITERS)        // 2560 float4
#define PIX_PER_BLOCK  (VEC_PER_BLOCK * 4 / WAY)// 2048 pixels (exact)
#define PIX_PER_ITER   (THREADS * 4 / WAY)      // 512 pixels (exact)
#define BLOCKS_PER_IMG (VEC_PER_IMG / VEC_PER_BLOCK) // 128

#define LOGITS_BYTES (LOGITS_PER_IMG * 4)       // 10240
#define SEG_BYTES    (PIX_PER_BLOCK * 4)        // 8192
#define TOTAL_TX     (LOGITS_BYTES + SEG_BYTES) // 18432
#define CHUNK_BYTES  (THREADS * 16)             // 10240 per iter

// Dynamic smem layout (byte offsets)
#define OFF_STAGE   0                            // 4 x 10240 = 40960
#define OFF_LOGITS  (OFF_STAGE + ITERS * CHUNK_BYTES)   // 40960
#define OFF_SEG     (OFF_LOGITS + LOGITS_BYTES)         // 51200
#define OFF_MBAR    (OFF_SEG + SEG_BYTES + 16)          // 59408 (8-aligned)
#define SMEM_TOTAL  (OFF_MBAR + 16)                     // 59424

__device__ __forceinline__ uint32_t smem_u32(const void* p) {
    uint32_t a;
    asm("{ .reg .u64 t; cvta.to.shared.u64 t, %1; cvt.u32.u64 %0, t; }"
        : "=r"(a) : "l"(p));
    return a;
}

__global__ void __launch_bounds__(THREADS)
sp_gather_kernel11(const float* __restrict__ logits,
                   const int* __restrict__ seg,
                   float4* __restrict__ out)
{
    extern __shared__ __align__(1024) char smem[];
    float4*   s_stage  = (float4*)(smem + OFF_STAGE);      // [ITERS][THREADS]
    float*    s_logits = (float*)(smem + OFF_LOGITS);
    int*      s_seg    = (int*)(smem + OFF_SEG);
    uint64_t* s_mbar   = (uint64_t*)(smem + OFF_MBAR);

    const int img = blockIdx.y;
    const int blk = blockIdx.x;
    const int tid = threadIdx.x;

    // ---- Staging via two cp.async.bulk G->S copies, one mbarrier ----
    if (tid == 0) {
        uint32_t mb = smem_u32(s_mbar);
        asm volatile("mbarrier.init.shared.b64 [%0], 1;" :: "r"(mb) : "memory");
    }
    __syncthreads();

    if (tid == 0) {
        uint32_t mb = smem_u32(s_mbar);
        asm volatile("mbarrier.arrive.expect_tx.shared.b64 _, [%0], %1;"
                     :: "r"(mb), "n"(TOTAL_TX) : "memory");
        uint32_t dl = smem_u32(s_logits);
        const void* sl = logits + (size_t)img * LOGITS_PER_IMG;
        asm volatile(
            "cp.async.bulk.shared::cta.global.mbarrier::complete_tx::bytes "
            "[%0], [%1], %2, [%3];"
            :: "r"(dl), "l"(sl), "n"(LOGITS_BYTES), "r"(mb) : "memory");
        uint32_t ds = smem_u32(s_seg);
        const void* ss = seg + (size_t)img * PIX_PER_IMG
                             + (size_t)blk * PIX_PER_BLOCK;
        asm volatile(
            "cp.async.bulk.shared::cta.global.mbarrier::complete_tx::bytes "
            "[%0], [%1], %2, [%3];"
            :: "r"(ds), "l"(ss), "n"(SEG_BYTES), "r"(mb) : "memory");
    }

    // Wait (acquire orders subsequent LDS after the TMA writes).
    {
        uint32_t mb = smem_u32(s_mbar);
        uint32_t done;
        asm volatile(
            "{\n\t"
            ".reg .pred p;\n\t"
            "mbarrier.try_wait.parity.acquire.cta.shared::cta.b64 p, [%1], 0;\n\t"
            "selp.b32 %0, 1, 0, p;\n\t"
            "}" : "=r"(done) : "r"(mb) : "memory");
        if (!done) {
            asm volatile(
                "{\n\t"
                ".reg .pred P1;\n\t"
                "WL_%=:\n\t"
                "mbarrier.try_wait.parity.acquire.cta.shared::cta.b64 P1, [%0], 0, 0x989680;\n\t"
                "@P1 bra.uni WD_%=;\n\t"
                "bra.uni WL_%=;\n\t"
                "WD_%=:\n\t"
                "}" :: "r"(mb) : "memory");
        }
    }

    // ---- Hot loop ----
    float4* out_blk = out + (size_t)img * VEC_PER_IMG
                          + (size_t)blk * VEC_PER_BLOCK;

    const int floc = tid << 2;            // 0..2556
    const int p0   = floc / 5;            // 0..511
    const int r    = floc - 5 * p0;       // constant channel remainder 0..4
    const int m    = 5 - r;
    const bool need_s1 = (r >= 2);        // s1 used only when m < 4

    // Phase A: all seg loads in flight, compute gather bases.
    int b0[ITERS], b1[ITERS];
#pragma unroll
    for (int it = 0; it < ITERS; ++it) {
        const int p = p0 + it * PIX_PER_ITER;   // compile-time offsets
        b0[it] = s_seg[p] * WAY + r;
        b1[it] = need_s1 ? (s_seg[p + 1] * WAY + r - 5) : 0;
    }

    // Phase B: gather -> STS (conflict-free) -> per-iter TMA bulk store.
#pragma unroll
    for (int it = 0; it < ITERS; ++it) {
        float v0 = s_logits[((0 < m) ? b0[it] : b1[it]) + 0];
        float v1 = s_logits[((1 < m) ? b0[it] : b1[it]) + 1];
        float v2 = s_logits[((2 < m) ? b0[it] : b1[it]) + 2];
        float v3 = s_logits[((3 < m) ? b0[it] : b1[it]) + 3];
        s_stage[it * THREADS + tid] = make_float4(v0, v1, v2, v3);
        __syncthreads();
        if (tid == 0) {
            asm volatile("fence.proxy.async.shared::cta;" ::: "memory");
            uint32_t src = smem_u32(&s_stage[it * THREADS]);
            const float4* dst = out_blk + it * THREADS;
            asm volatile(
                "cp.async.bulk.global.shared::cta.bulk_group [%0], [%1], %2;"
                :: "l"(dst), "r"(src), "n"(CHUNK_BYTES) : "memory");
            asm volatile("cp.async.bulk.commit_group;" ::: "memory");
        }
    }

    // Drain all bulk stores (smem reads must finish before block exit).
    if (tid == 0)
        asm volatile("cp.async.bulk.wait_group.read 0;" ::: "memory");
    __syncthreads();
}

extern "C" void kernel_launch(void* const* d_in, const int* in_sizes, int n_in,
                              void* d_out, int out_size)
{
    const float* logits = (const float*)d_in[0];
    const int*   seg    = (const int*)d_in[1];
    float4*      out    = (float4*)d_out;

    static int smem_set = 0;
    if (!smem_set) {
        cudaFuncSetAttribute(sp_gather_kernel11,
                             cudaFuncAttributeMaxDynamicSharedMemorySize,
                             SMEM_TOTAL);
        smem_set = 1;
    }

    dim3 grid(BLOCKS_PER_IMG, N_IMG);
    sp_gather_kernel11<<<grid, THREADS, SMEM_TOTAL>>>(logits, seg, out);
}

// round 12
// speedup vs baseline: 1.1787x; 1.1787x over previous
#include <cuda_runtime.h>
#include <cuda_bf16.h>
#include <cstdint>

// Gather: out[i, y, x, c] = logits[i * N_SP + segments[i, y, x], c]
//   logits:   [16*512, 5] fp32 (10 KB per image, TMA bulk-loaded into smem)
//   segments: [16, 512, 512] int32 (4 KB tile per block, TMA bulk-loaded)
//   out:      [16, 512, 512, 5] fp32
//
// R12: residency experiment. Identical structure to R9 (best, 19.1us
// internal) but 160-thread blocks / ITERS=8 / 4096 blocks -> 12 resident
// blocks per SM instead of 6. Total threads/SM, per-warp work, and LSU work
// are all unchanged; only the number of independently-staged tiles in flight
// doubles, so each block's ~1.8us staging latency (fit from R7/R9) hides
// behind 11 neighbors' compute, and the last-wave drain granularity halves.

#define N_IMG 16
#define SIZE  512
#define N_SP  512
#define WAY   5
#define PIX_PER_IMG    (SIZE * SIZE)            // 262144
#define VEC_PER_IMG    (PIX_PER_IMG * WAY / 4)  // 327680 float4
#define LOGITS_PER_IMG (N_SP * WAY)             // 2560 floats = 10240 B

#define THREADS 160
#define ITERS 8
#define VEC_PER_BLOCK  (THREADS * ITERS)        // 1280 float4
#define PIX_PER_BLOCK  (VEC_PER_BLOCK * 4 / WAY)// 1024 pixels (exact)
#define PIX_PER_ITER   (THREADS * 4 / WAY)      // 128 pixels
#define BLOCKS_PER_IMG (VEC_PER_IMG / VEC_PER_BLOCK) // 256

#define LOGITS_BYTES (LOGITS_PER_IMG * 4)       // 10240
#define SEG_BYTES    (PIX_PER_BLOCK * 4)        // 4096
#define TOTAL_TX     (LOGITS_BYTES + SEG_BYTES) // 14336

__device__ __forceinline__ uint32_t smem_u32(const void* p) {
    uint32_t a;
    asm("{ .reg .u64 t; cvta.to.shared.u64 t, %1; cvt.u32.u64 %0, t; }"
        : "=r"(a) : "l"(p));
    return a;
}

__global__ void __launch_bounds__(THREADS)
sp_gather_kernel12(const float* __restrict__ logits,
                   const int* __restrict__ seg,
                   float4* __restrict__ out)
{
    __shared__ __align__(16) float    s_logits[LOGITS_PER_IMG];
    __shared__ __align__(16) int      s_seg[PIX_PER_BLOCK + 4]; // +pad vs spec. loads
    __shared__ __align__(8)  uint64_t s_mbar;

    const int img = blockIdx.y;
    const int blk = blockIdx.x;
    const int tid = threadIdx.x;

    // ---- Staging via two cp.async.bulk G->S copies, one mbarrier ----
    if (tid == 0) {
        uint32_t mb = smem_u32(&s_mbar);
        asm volatile("mbarrier.init.shared.b64 [%0], 1;" :: "r"(mb) : "memory");
    }
    __syncthreads();

    if (tid == 0) {
        uint32_t mb = smem_u32(&s_mbar);
        asm volatile("mbarrier.arrive.expect_tx.shared.b64 _, [%0], %1;"
                     :: "r"(mb), "n"(TOTAL_TX) : "memory");
        uint32_t dl = smem_u32(s_logits);
        const void* sl = logits + (size_t)img * LOGITS_PER_IMG;
        asm volatile(
            "cp.async.bulk.shared::cta.global.mbarrier::complete_tx::bytes "
            "[%0], [%1], %2, [%3];"
            :: "r"(dl), "l"(sl), "n"(LOGITS_BYTES), "r"(mb) : "memory");
        uint32_t ds = smem_u32(s_seg);
        const void* ss = seg + (size_t)img * PIX_PER_IMG
                             + (size_t)blk * PIX_PER_BLOCK;
        asm volatile(
            "cp.async.bulk.shared::cta.global.mbarrier::complete_tx::bytes "
            "[%0], [%1], %2, [%3];"
            :: "r"(ds), "l"(ss), "n"(SEG_BYTES), "r"(mb) : "memory");
    }

    // Wait (acquire orders subsequent LDS after the TMA writes).
    {
        uint32_t mb = smem_u32(&s_mbar);
        uint32_t done;
        asm volatile(
            "{\n\t"
            ".reg .pred p;\n\t"
            "mbarrier.try_wait.parity.acquire.cta.shared::cta.b64 p, [%1], 0;\n\t"
            "selp.b32 %0, 1, 0, p;\n\t"
            "}" : "=r"(done) : "r"(mb) : "memory");
        if (!done) {
            asm volatile(
                "{\n\t"
                ".reg .pred P1;\n\t"
                "WL_%=:\n\t"
                "mbarrier.try_wait.parity.acquire.cta.shared::cta.b64 P1, [%0], 0, 0x989680;\n\t"
                "@P1 bra.uni WD_%=;\n\t"
                "bra.uni WL_%=;\n\t"
                "WD_%=:\n\t"
                "}" :: "r"(mb) : "memory");
        }
    }

    // ---- Hot loop: smem gather + coalesced STG.128 ----
    float4* out_img = out + (size_t)img * VEC_PER_IMG;
    const int jbase = blk * VEC_PER_BLOCK + tid;

    const int floc = tid << 2;            // 0..636
    const int p0   = floc / 5;            // 0..127
    const int r    = floc - 5 * p0;       // constant channel remainder 0..4
    const int m    = 5 - r;
    const bool need_s1 = (r >= 2);        // s1 used only when m < 4

#pragma unroll
    for (int it = 0; it < ITERS; ++it) {
        const int p = p0 + it * PIX_PER_ITER;
        int b0 = s_seg[p] * WAY + r;
        int b1 = need_s1 ? (s_seg[p + 1] * WAY + r - 5) : 0;

        float v0 = s_logits[((0 < m) ? b0 : b1) + 0];
        float v1 = s_logits[((1 < m) ? b0 : b1) + 1];
        float v2 = s_logits[((2 < m) ? b0 : b1) + 2];
        float v3 = s_logits[((3 < m) ? b0 : b1) + 3];

        out_img[jbase + it * THREADS] = make_float4(v0, v1, v2, v3);
    }
}

extern "C" void kernel_launch(void* const* d_in, const int* in_sizes, int n_in,
                              void* d_out, int out_size)
{
    const float* logits = (const float*)d_in[0];
    const int*   seg    = (const int*)d_in[1];
    float4*      out    = (float4*)d_out;

    dim3 grid(BLOCKS_PER_IMG, N_IMG);
    sp_gather_kernel12<<<grid, THREADS>>>(logits, seg, out);
}

// round 13
// speedup vs baseline: 1.2964x; 1.0998x over previous
#include <cuda_runtime.h>
#include <cuda_bf16.h>
#include <cstdint>

// Gather: out[i, y, x, c] = logits[i * N_SP + segments[i, y, x], c]
//   logits:   [16*512, 5] fp32 (10 KB per image, TMA-staged once per block)
//   segments: [16, 512, 512] int32 (1024-px chunks, double-buffered TMA)
//   out:      [16, 512, 512, 5] fp32
//
// R13: single-wave persistent blocks. Every prior geometry was stuck at 2.31
// waves (occ ~72% = 77% packing). Grid (55,16)=880 blocks at 6/SM (888 slots)
// -> all blocks resident from t=0, no wave quantization. Each block loops
// over its 4-5 chunks of one image with double-buffered TMA seg prefetch;
// logits staged once. Hot loop = proven R9 body (r-constant lanes,
// predicated s1, coalesced STG.128). launch_bounds(320,6) pins regs<=32.

#define N_IMG 16
#define SIZE  512
#define N_SP  512
#define WAY   5
#define PIX_PER_IMG    (SIZE * SIZE)            // 262144
#define VEC_PER_IMG    (PIX_PER_IMG * WAY / 4)  // 327680 float4
#define LOGITS_PER_IMG (N_SP * WAY)             // 2560 floats = 10240 B

#define THREADS 320
#define BLOCKS_PER_IMG 55                       // 55*16 = 880 <= 148*6 = 888
#define CHUNK_PIX  1024
#define CHUNK_VEC  1280                         // float4 per chunk
#define ITERS 4                                 // 320*4 = 1280 float4
#define PIX_PER_ITER 256                        // 320*4/5, exact
#define CHUNKS_PER_IMG (PIX_PER_IMG / CHUNK_PIX) // 256

#define LOGITS_BYTES (LOGITS_PER_IMG * 4)       // 10240
#define SEG_BYTES    (CHUNK_PIX * 4)            // 4096
#define FIRST_TX     (LOGITS_BYTES + SEG_BYTES) // 14336

__device__ __forceinline__ uint32_t smem_u32(const void* p) {
    uint32_t a;
    asm("{ .reg .u64 t; cvta.to.shared.u64 t, %1; cvt.u32.u64 %0, t; }"
        : "=r"(a) : "l"(p));
    return a;
}

__device__ __forceinline__ void mbar_wait(uint32_t mb, int parity) {
    uint32_t done;
    asm volatile(
        "{\n\t"
        ".reg .pred p;\n\t"
        "mbarrier.try_wait.parity.acquire.cta.shared::cta.b64 p, [%1], %2;\n\t"
        "selp.b32 %0, 1, 0, p;\n\t"
        "}" : "=r"(done) : "r"(mb), "r"(parity) : "memory");
    if (!done) {
        asm volatile(
            "{\n\t"
            ".reg .pred P1;\n\t"
            "WL_%=:\n\t"
            "mbarrier.try_wait.parity.acquire.cta.shared::cta.b64 P1, [%0], %1, 0x989680;\n\t"
            "@P1 bra.uni WD_%=;\n\t"
            "bra.uni WL_%=;\n\t"
            "WD_%=:\n\t"
            "}" :: "r"(mb), "r"(parity) : "memory");
    }
}

__global__ void __launch_bounds__(THREADS, 6)
sp_gather_kernel13(const float* __restrict__ logits,
                   const int* __restrict__ seg,
                   float4* __restrict__ out)
{
    __shared__ __align__(16) float    s_logits[LOGITS_PER_IMG];
    __shared__ __align__(16) int      s_seg[2][CHUNK_PIX + 4];
    __shared__ __align__(8)  uint64_t s_mbar[2];

    const int img = blockIdx.y;
    const int blk = blockIdx.x;          // 0..54
    const int tid = threadIdx.x;

    const uint32_t mb0 = smem_u32(&s_mbar[0]);
    const uint32_t mb1 = smem_u32(&s_mbar[1]);

    if (tid == 0) {
        asm volatile("mbarrier.init.shared.b64 [%0], 1;" :: "r"(mb0) : "memory");
        asm volatile("mbarrier.init.shared.b64 [%0], 1;" :: "r"(mb1) : "memory");
    }
    __syncthreads();

    const int* seg_img = seg + (size_t)img * PIX_PER_IMG;

    // Prologue: logits + first chunk's seg into buf0, one mbarrier.
    if (tid == 0) {
        asm volatile("mbarrier.arrive.expect_tx.shared.b64 _, [%0], %1;"
                     :: "r"(mb0), "n"(FIRST_TX) : "memory");
        uint32_t dl = smem_u32(s_logits);
        const void* sl = logits + (size_t)img * LOGITS_PER_IMG;
        asm volatile(
            "cp.async.bulk.shared::cta.global.mbarrier::complete_tx::bytes "
            "[%0], [%1], %2, [%3];"
            :: "r"(dl), "l"(sl), "n"(LOGITS_BYTES), "r"(mb0) : "memory");
        uint32_t ds = smem_u32(&s_seg[0][0]);
        const void* ss = seg_img + (size_t)blk * CHUNK_PIX;
        asm volatile(
            "cp.async.bulk.shared::cta.global.mbarrier::complete_tx::bytes "
            "[%0], [%1], %2, [%3];"
            :: "r"(ds), "l"(ss), "n"(SEG_BYTES), "r"(mb0) : "memory");
    }

    // Per-thread constants (one small division total).
    const int floc = tid << 2;            // 0..1276
    const int p0   = floc / 5;            // 0..255
    const int r    = floc - 5 * p0;       // constant channel remainder 0..4
    const int m    = 5 - r;
    const bool need_s1 = (r >= 2);

    float4* out_img = out + (size_t)img * VEC_PER_IMG;

    int ph0 = 0, ph1 = 0;
    int t = 0;
#pragma unroll 1
    for (int c = blk; c < CHUNKS_PER_IMG; c += BLOCKS_PER_IMG, ++t) {
        const int buf = t & 1;

        // All warps finished reading buf^1 in iteration t-1; safe to refill it.
        __syncthreads();
        if (tid == 0) {
            int cn = c + BLOCKS_PER_IMG;
            if (cn < CHUNKS_PER_IMG) {
                uint32_t mbn = buf ? mb0 : mb1;
                asm volatile("mbarrier.arrive.expect_tx.shared.b64 _, [%0], %1;"
                             :: "r"(mbn), "n"(SEG_BYTES) : "memory");
                uint32_t ds = smem_u32(&s_seg[buf ^ 1][0]);
                const void* ss = seg_img + (size_t)cn * CHUNK_PIX;
                asm volatile(
                    "cp.async.bulk.shared::cta.global.mbarrier::complete_tx::bytes "
                    "[%0], [%1], %2, [%3];"
                    :: "r"(ds), "l"(ss), "n"(SEG_BYTES), "r"(mbn) : "memory");
            }
        }

        // Wait for current chunk's data (buf0 first wait also covers logits).
        if (buf == 0) { mbar_wait(mb0, ph0); ph0 ^= 1; }
        else          { mbar_wait(mb1, ph1); ph1 ^= 1; }

        const int* sseg = &s_seg[buf][0];
        float4* out_chunk = out_img + (size_t)c * CHUNK_VEC;

#pragma unroll
        for (int it = 0; it < ITERS; ++it) {
            const int p = p0 + it * PIX_PER_ITER;
            int b0 = sseg[p] * WAY + r;
            int b1 = need_s1 ? (sseg[p + 1] * WAY + r - 5) : 0;

            float v0 = s_logits[((0 < m) ? b0 : b1) + 0];
            float v1 = s_logits[((1 < m) ? b0 : b1) + 1];
            float v2 = s_logits[((2 < m) ? b0 : b1) + 2];
            float v3 = s_logits[((3 < m) ? b0 : b1) + 3];

            out_chunk[it * THREADS + tid] = make_float4(v0, v1, v2, v3);
        }
    }
}

extern "C" void kernel_launch(void* const* d_in, const int* in_sizes, int n_in,
                              void* d_out, int out_size)
{
    const float* logits = (const float*)d_in[0];
    const int*   seg    = (const int*)d_in[1];
    float4*      out    = (float4*)d_out;

    dim3 grid(BLOCKS_PER_IMG, N_IMG);
    sp_gather_kernel13<<<grid, THREADS>>>(logits, seg, out);
}

// round 14
// speedup vs baseline: 1.3005x; 1.0031x over previous
#include <cuda_runtime.h>
#include <cuda_bf16.h>
#include <cstdint>

// Gather: out[i, y, x, c] = logits[i * N_SP + segments[i, y, x], c]
//   logits:   [16*512, 5] fp32 (10 KB per image, TMA-staged once per block)
//   segments: [16, 512, 512] int32 (TMA-staged, 5 single-use buffers)
//   out:      [16, 512, 512, 5] fp32
//
// R14: single-wave persistent blocks (R13) with
//  - balanced unit split: unit = 256 px; 1024 units/img over 55 blocks ->
//    19/18 units per block (makespan tax 7.5% -> 2.1%). A unit's 1280 floats
//    = 5*256 exactly, so no cross-unit seg reads (no pad, no clamp).
//  - zero in-loop __syncthreads: all seg TMA loads issued up-front into 5
//    single-use buffers (no reuse -> no refill barrier); per chunk just one
//    mbarrier fast-path wait.

#define N_IMG 16
#define SIZE  512
#define N_SP  512
#define WAY   5
#define PIX_PER_IMG    (SIZE * SIZE)            // 262144
#define VEC_PER_IMG    (PIX_PER_IMG * WAY / 4)  // 327680 float4
#define LOGITS_PER_IMG (N_SP * WAY)             // 2560 floats = 10240 B

#define THREADS 320
#define BLOCKS_PER_IMG 55                       // 880 blocks <= 148*6 = 888
#define UNIT_PIX   256                          // one iter: 320 float4 = 1280 floats
#define UNIT_VEC   320
#define UNITS_PER_IMG (PIX_PER_IMG / UNIT_PIX)  // 1024
#define UNITS_PER_CHUNK 4
#define MAX_CHUNKS 5                            // ceil(19/4)

#define LOGITS_BYTES (LOGITS_PER_IMG * 4)       // 10240
#define CHUNK_PIX   (UNITS_PER_CHUNK * UNIT_PIX) // 1024
#define CHUNK_BYTES (CHUNK_PIX * 4)              // 4096

// 1024 = 55*18 + 34 -> first 34 blocks get 19 units, rest get 18
#define BIG_BLOCKS 34

__device__ __forceinline__ uint32_t smem_u32(const void* p) {
    uint32_t a;
    asm("{ .reg .u64 t; cvta.to.shared.u64 t, %1; cvt.u32.u64 %0, t; }"
        : "=r"(a) : "l"(p));
    return a;
}

__device__ __forceinline__ void mbar_wait0(uint32_t mb) {
    uint32_t done;
    asm volatile(
        "{\n\t"
        ".reg .pred p;\n\t"
        "mbarrier.try_wait.parity.acquire.cta.shared::cta.b64 p, [%1], 0;\n\t"
        "selp.b32 %0, 1, 0, p;\n\t"
        "}" : "=r"(done) : "r"(mb) : "memory");
    if (!done) {
        asm volatile(
            "{\n\t"
            ".reg .pred P1;\n\t"
            "WL_%=:\n\t"
            "mbarrier.try_wait.parity.acquire.cta.shared::cta.b64 P1, [%0], 0, 0x989680;\n\t"
            "@P1 bra.uni WD_%=;\n\t"
            "bra.uni WL_%=;\n\t"
            "WD_%=:\n\t"
            "}" :: "r"(mb) : "memory");
    }
}

__global__ void __launch_bounds__(THREADS, 6)
sp_gather_kernel14(const float* __restrict__ logits,
                   const int* __restrict__ seg,
                   float4* __restrict__ out)
{
    __shared__ __align__(16) float    s_logits[LOGITS_PER_IMG];
    __shared__ __align__(16) int      s_seg[MAX_CHUNKS][CHUNK_PIX];
    __shared__ __align__(8)  uint64_t s_mbar[MAX_CHUNKS];

    const int img = blockIdx.y;
    const int blk = blockIdx.x;          // 0..54
    const int tid = threadIdx.x;

    // Balanced unit range for this block.
    const int big    = (blk < BIG_BLOCKS);
    const int ucount = 18 + big;                              // 18 or 19
    const int ustart = 18 * blk + (big ? blk : BIG_BLOCKS);
    const int nch    = (ucount + UNITS_PER_CHUNK - 1) / UNITS_PER_CHUNK; // 5

    if (tid == 0) {
#pragma unroll
        for (int c = 0; c < MAX_CHUNKS; ++c) {
            uint32_t mb = smem_u32(&s_mbar[c]);
            asm volatile("mbarrier.init.shared.b64 [%0], 1;" :: "r"(mb) : "memory");
        }
    }
    __syncthreads();   // the only block-wide barrier

    const int* seg_img = seg + (size_t)img * PIX_PER_IMG;

    // Issue ALL TMA loads up-front (engine-queued; no L1tex involvement).
    if (tid == 0) {
        // chunk 0's barrier also covers the logits copy
        {
            uint32_t mb = smem_u32(&s_mbar[0]);
            uint32_t tx = LOGITS_BYTES + CHUNK_BYTES;
            asm volatile("mbarrier.arrive.expect_tx.shared.b64 _, [%0], %1;"
                         :: "r"(mb), "r"(tx) : "memory");
            uint32_t dl = smem_u32(s_logits);
            const void* sl = logits + (size_t)img * LOGITS_PER_IMG;
            asm volatile(
                "cp.async.bulk.shared::cta.global.mbarrier::complete_tx::bytes "
                "[%0], [%1], %2, [%3];"
                :: "r"(dl), "l"(sl), "n"(LOGITS_BYTES), "r"(mb) : "memory");
            uint32_t ds = smem_u32(&s_seg[0][0]);
            const void* ss = seg_img + (size_t)ustart * UNIT_PIX;
            asm volatile(
                "cp.async.bulk.shared::cta.global.mbarrier::complete_tx::bytes "
                "[%0], [%1], %2, [%3];"
                :: "r"(ds), "l"(ss), "n"(CHUNK_BYTES), "r"(mb) : "memory");
        }
#pragma unroll
        for (int c = 1; c < MAX_CHUNKS; ++c) {
            int uc = ucount - c * UNITS_PER_CHUNK;            // units in chunk c
            if (uc <= 0) break;
            if (uc > UNITS_PER_CHUNK) uc = UNITS_PER_CHUNK;
            uint32_t bytes = uc * UNIT_PIX * 4;
            uint32_t mb = smem_u32(&s_mbar[c]);
            asm volatile("mbarrier.arrive.expect_tx.shared.b64 _, [%0], %1;"
                         :: "r"(mb), "r"(bytes) : "memory");
            uint32_t ds = smem_u32(&s_seg[c][0]);
            const void* ss = seg_img + (size_t)(ustart + c * UNITS_PER_CHUNK) * UNIT_PIX;
            asm volatile(
                "cp.async.bulk.shared::cta.global.mbarrier::complete_tx::bytes "
                "[%0], [%1], %2, [%3];"
                :: "r"(ds), "l"(ss), "r"(bytes), "r"(mb) : "memory");
        }
    }

    // Per-thread constants.
    const int floc = tid << 2;            // 0..1276 within a unit
    const int p0   = floc / 5;            // 0..255
    const int r    = floc - 5 * p0;       // constant channel remainder 0..4
    const int m    = 5 - r;
    const bool need_s1 = (r >= 2);        // max p0 with need_s1 is 254 -> in-unit

    float4* out_img = out + (size_t)img * VEC_PER_IMG;

    int u = 0;
#pragma unroll 1
    for (int c = 0; c < nch; ++c) {
        mbar_wait0(smem_u32(&s_mbar[c]));
        int ulim = c * UNITS_PER_CHUNK + UNITS_PER_CHUNK;
        if (ulim > ucount) ulim = ucount;
#pragma unroll 1
        for (; u < ulim; ++u) {
            const int* sseg = &s_seg[c][(u - c * UNITS_PER_CHUNK) * UNIT_PIX];
            int b0 = sseg[p0] * WAY + r;
            int b1 = need_s1 ? (sseg[p0 + 1] * WAY + r - 5) : 0;

            float v0 = s_logits[((0 < m) ? b0 : b1) + 0];
            float v1 = s_logits[((1 < m) ? b0 : b1) + 1];
            float v2 = s_logits[((2 < m) ? b0 : b1) + 2];
            float v3 = s_logits[((3 < m) ? b0 : b1) + 3];

            out_img[(size_t)(ustart + u) * UNIT_VEC + tid] =
                make_float4(v0, v1, v2, v3);
        }
    }
}

extern "C" void kernel_launch(void* const* d_in, const int* in_sizes, int n_in,
                              void* d_out, int out_size)
{
    const float* logits = (const float*)d_in[0];
    const int*   seg    = (const int*)d_in[1];
    float4*      out    = (float4*)d_out;

    dim3 grid(BLOCKS_PER_IMG, N_IMG);
    sp_gather_kernel14<<<grid, THREADS>>>(logits, seg, out);
}